// round 11
// baseline (speedup 1.0000x reference)
#include <cuda_runtime.h>
#include <cuda.h>
#include <cstdint>

// AlignedLinear: y[n, o*9+d] = alpha * sum_i x[n, i*9+d] * K[r(d), i, o]
// r(d)=0 d=0; 1 d=1..3; 2 d=4..8.
//
// R11: MT=12 nodes/CTA -> tile 55296 B -> 4 CTAs/SM (16 warps, occ 25%).
// TMA in/out (SW128, view [32f][node][36seg], swizzle key=(node+4*seg)&7).
// m16 fragments cover node rows g and g+8; rows 12..15 are padding:
// their A reads are discarded, their WRITEBACK IS PREDICATED OFF (g<4) —
// unconditional writeback was R10's corruption bug (rows 12..15 alias the
// next seg's chunks 0..3). DC=5 irrep split 3+2 to fit 128 regs.
// B fragments from fragment-major tf32 global buffer (alpha folded),
// prefetch depth 2. Outputs overwrite dead words in the swizzled tile.

#define MT        12
#define DIMT      9
#define MUL       128
#define ROWF      1152
#define TILE_BYTES (MT * ROWF * 4)      // 55296
#define SEG_STRIDE (MT * 128)           // bytes per seg in smem = 1536
#define NTHREADS  128
#define ALPHA_F   0.08838834764831845f  // sqrt(1/128)

#define KB_WORDS  (3 * 16 * 16 * 64)
__device__ __align__(16) uint32_t g_kbuf[KB_WORDS];

static __device__ __forceinline__ uint32_t f2tf32(float f) {
    uint32_t u;
    asm("cvt.rna.tf32.f32 %0, %1;" : "=r"(u) : "f"(f));
    return u;
}

static __device__ __forceinline__ void mma_tf32(float c[4],
    uint32_t a0, uint32_t a1, uint32_t a2, uint32_t a3,
    uint32_t b0, uint32_t b1)
{
    asm volatile(
        "mma.sync.aligned.m16n8k8.row.col.f32.tf32.tf32.f32 "
        "{%0,%1,%2,%3}, {%4,%5,%6,%7}, {%8,%9}, {%0,%1,%2,%3};"
        : "+f"(c[0]), "+f"(c[1]), "+f"(c[2]), "+f"(c[3])
        : "r"(a0), "r"(a1), "r"(a2), "r"(a3), "r"(b0), "r"(b1));
}

// ---- Prep: K[r][i][o] fp32 -> fragment-major tf32 (RNA), alpha folded ----
__global__ void prep_k_kernel(const float* __restrict__ kern)
{
    int idx = blockIdx.x * blockDim.x + threadIdx.x;
    if (idx >= KB_WORDS) return;
    int j    = idx & 1;
    int lane = (idx >> 1) & 31;
    int nt   = (idx >> 6) & 15;
    int k8   = (idx >> 10) & 15;
    int r    = idx >> 14;
    int k = k8 * 8 + (lane & 3) + 4 * j;
    int o = nt * 8 + (lane >> 2);
    g_kbuf[idx] = f2tf32(ALPHA_F * kern[(r * MUL + k) * MUL + o]);
}

// Swizzled byte offset (relative to node-row base) of word w = 9k+d.
// chunk = seg*MT + node; key = (chunk&7)<<4 = ((node + 4*seg)&7)<<4.
// Rows g and g+8 share the key (8 ≡ 0 mod 8); row g+8 is +1024 B.
static __device__ __forceinline__ uint32_t swz(int w, int g) {
    uint32_t s  = (uint32_t)w >> 5;
    uint32_t ky = (((uint32_t)g + 4u * s) & 7u) << 4;
    return s * (uint32_t)SEG_STRIDE + ((((uint32_t)w & 31u) << 2) ^ ky);
}

static __device__ __forceinline__ uint32_t lds32(uint32_t a) {
    uint32_t v;
    asm volatile("ld.shared.b32 %0, [%1];" : "=r"(v) : "r"(a));
    return v;
}
static __device__ __forceinline__ void sts32(uint32_t a, float v) {
    asm volatile("st.shared.b32 [%0], %1;" :: "r"(a), "f"(v));
}

template<int R, int D0, int DC>
static __device__ __forceinline__ void process_group(
    uint32_t tbase, int g, int tg, int lane, int warp)
{
    const uint2* kb = reinterpret_cast<const uint2*>(g_kbuf)
                    + ((size_t)R * 256 + warp * 4) * 32 + lane;
    const uint32_t rowb = tbase + (uint32_t)g * 128u;
    const bool hi_valid = (g < MT - 8);   // node g+8 exists (rows 12..15: pad)

    float c[DC][4][4];
    #pragma unroll
    for (int dd = 0; dd < DC; ++dd)
        #pragma unroll
        for (int nt = 0; nt < 4; ++nt)
            #pragma unroll
            for (int i = 0; i < 4; ++i) c[dd][nt][i] = 0.f;

    // B prefetch depth 2
    uint2 buf[2][4];
    #pragma unroll
    for (int nt = 0; nt < 4; ++nt) buf[0][nt] = __ldg(kb + nt * 32);
    #pragma unroll
    for (int nt = 0; nt < 4; ++nt) buf[1][nt] = __ldg(kb + 512 + nt * 32);

    #pragma unroll 2
    for (int k8 = 0; k8 < 16; ++k8) {
        uint2 cur[4];
        #pragma unroll
        for (int nt = 0; nt < 4; ++nt) cur[nt] = buf[k8 & 1][nt];
        if (k8 < 14) {
            const uint2* kbn = kb + (k8 + 2) * 512;
            #pragma unroll
            for (int nt = 0; nt < 4; ++nt)
                buf[k8 & 1][nt] = __ldg(kbn + nt * 32);
        }
        #pragma unroll
        for (int dd = 0; dd < DC; ++dd) {
            const int w0 = 72 * k8 + 9 * tg + (D0 + dd);
            const uint32_t o0 = rowb + swz(w0,      g);
            const uint32_t o1 = rowb + swz(w0 + 36, g);
            uint32_t a0 = lds32(o0);
            uint32_t a1 = lds32(o0 + 1024);   // pad rows: garbage, discarded
            uint32_t a2 = lds32(o1);
            uint32_t a3 = lds32(o1 + 1024);
            #pragma unroll
            for (int nt = 0; nt < 4; ++nt)
                mma_tf32(c[dd][nt], a0, a1, a2, a3, cur[nt].x, cur[nt].y);
        }
    }

    __syncthreads();   // all warps done reading this group's X words

    // Overwrite the dead words (o*9+d of this group) in the swizzled tile.
    // Hi rows (node g+8) only exist for g<4 — R10 bug was writing them always.
    #pragma unroll
    for (int dd = 0; dd < DC; ++dd) {
        #pragma unroll
        for (int nt = 0; nt < 4; ++nt) {
            const int o = warp * 32 + nt * 8 + 2 * tg;
            const int w = o * 9 + (D0 + dd);
            const uint32_t p0 = rowb + swz(w,     g);
            const uint32_t p1 = rowb + swz(w + 9, g);
            sts32(p0, c[dd][nt][0]);
            sts32(p1, c[dd][nt][1]);
            if (hi_valid) {
                sts32(p0 + 1024, c[dd][nt][2]);
                sts32(p1 + 1024, c[dd][nt][3]);
            }
        }
    }
}

__global__ void __launch_bounds__(NTHREADS, 4)
aligned_linear_tma(const __grid_constant__ CUtensorMap tmx,
                   const __grid_constant__ CUtensorMap tmy)
{
    extern __shared__ uint32_t dyn[];
    const uint32_t raw   = (uint32_t)__cvta_generic_to_shared(dyn);
    const uint32_t tbase = (raw + 1023u) & ~1023u;   // SW128 needs 1KB align
    const uint32_t bar   = tbase + TILE_BYTES;

    const int tid  = threadIdx.x;
    const int lane = tid & 31;
    const int warp = tid >> 5;
    const int g    = lane >> 2;
    const int tg   = lane & 3;
    const int node0 = blockIdx.x * MT;

    if (tid == 0)
        asm volatile("mbarrier.init.shared.b64 [%0], 1;" :: "r"(bar));
    __syncthreads();

    if (tid == 0) {
        asm volatile("mbarrier.arrive.expect_tx.shared.b64 _, [%0], %1;"
                     :: "r"(bar), "r"(TILE_BYTES));
        asm volatile(
            "cp.async.bulk.tensor.3d.shared::cta.global.tile"
            ".mbarrier::complete_tx::bytes [%0], [%1, {%2, %3, %4}], [%5];"
            :: "r"(tbase), "l"(&tmx),
               "r"(0), "r"(node0), "r"(0), "r"(bar) : "memory");
    }
    asm volatile(
        "{\n\t.reg .pred P;\n\t"
        "WL_%=:\n\t"
        "mbarrier.try_wait.parity.acquire.cta.shared::cta.b64 P, [%0], %1, 0x989680;\n\t"
        "@P bra WD_%=;\n\t"
        "bra WL_%=;\n\t"
        "WD_%=:\n\t}"
        :: "r"(bar), "r"(0u) : "memory");

    process_group<0, 0, 1>(tbase, g, tg, lane, warp);
    process_group<1, 1, 3>(tbase, g, tg, lane, warp);
    process_group<2, 4, 3>(tbase, g, tg, lane, warp);
    process_group<2, 7, 2>(tbase, g, tg, lane, warp);

    __syncthreads();   // all writebacks visible

    if (tid == 0) {
        asm volatile("fence.proxy.async;" ::: "memory");
        asm volatile(
            "cp.async.bulk.tensor.3d.global.shared::cta.tile.bulk_group "
            "[%0, {%1, %2, %3}], [%4];"
            :: "l"(&tmy), "r"(0), "r"(node0), "r"(0), "r"(tbase) : "memory");
        asm volatile("cp.async.bulk.commit_group;");
        asm volatile("cp.async.bulk.wait_group 0;");
    }
}

extern "C" void kernel_launch(void* const* d_in, const int* in_sizes, int n_in,
                              void* d_out, int out_size)
{
    const float* x = (const float*)d_in[0];
    const float* k = (const float*)d_in[1];
    float* y = (float*)d_out;
    int n_nodes = in_sizes[0] / ROWF;

    prep_k_kernel<<<(KB_WORDS + 255) / 256, 256>>>(k);

    typedef CUresult (*enc_t)(CUtensorMap*, CUtensorMapDataType, cuuint32_t,
                              void*, const cuuint64_t*, const cuuint64_t*,
                              const cuuint32_t*, const cuuint32_t*,
                              CUtensorMapInterleave, CUtensorMapSwizzle,
                              CUtensorMapL2promotion, CUtensorMapFloatOOBfill);
    enc_t enc = nullptr;
    {
        void* p = nullptr;
        cudaDriverEntryPointQueryResult qr;
        cudaGetDriverEntryPointByVersion("cuTensorMapEncodeTiled", &p, 12000,
                                         cudaEnableDefault, &qr);
        enc = (enc_t)p;
    }

    // View: [32 floats][node][36 segs]; box [32, MT, 36]; SW128.
    // Loads zero-fill OOB nodes; stores clip (50000 % 12 != 0 is safe).
    cuuint64_t dims[3]    = {32, (cuuint64_t)n_nodes, 36};
    cuuint64_t strides[2] = {(cuuint64_t)ROWF * 4, 128};
    cuuint32_t box[3]     = {32, MT, 36};
    cuuint32_t es[3]      = {1, 1, 1};

    CUtensorMap tmx, tmy;
    enc(&tmx, CU_TENSOR_MAP_DATA_TYPE_FLOAT32, 3, (void*)x,
        dims, strides, box, es,
        CU_TENSOR_MAP_INTERLEAVE_NONE, CU_TENSOR_MAP_SWIZZLE_128B,
        CU_TENSOR_MAP_L2_PROMOTION_L2_128B, CU_TENSOR_MAP_FLOAT_OOB_FILL_NONE);
    enc(&tmy, CU_TENSOR_MAP_DATA_TYPE_FLOAT32, 3, (void*)y,
        dims, strides, box, es,
        CU_TENSOR_MAP_INTERLEAVE_NONE, CU_TENSOR_MAP_SWIZZLE_128B,
        CU_TENSOR_MAP_L2_PROMOTION_L2_128B, CU_TENSOR_MAP_FLOAT_OOB_FILL_NONE);

    size_t smem = TILE_BYTES + 1024 + 16;   // align slack + mbarrier
    cudaFuncSetAttribute(aligned_linear_tma,
                         cudaFuncAttributeMaxDynamicSharedMemorySize,
                         (int)smem);

    int grid = (n_nodes + MT - 1) / MT;
    aligned_linear_tma<<<grid, NTHREADS, smem>>>(tmx, tmy);
}